// round 4
// baseline (speedup 1.0000x reference)
#include <cuda_runtime.h>
#include <cuda_bf16.h>
#include <math.h>

#define N_NODES 100000
#define E_EDGES 3200000
#define HDIM 64
#define NTYPES 5
#define NGRAPH 256
#define ODIM 12
#define NSTEPS 6
#define TCOLS (NTYPES * HDIM)   // 320

// ---------------- static device scratch ----------------
__device__ float d_T[(size_t)N_NODES * TCOLS];     // 128 MB
__device__ float d_h[(size_t)N_NODES * HDIM];
__device__ float d_out0[(size_t)N_NODES * HDIM];
__device__ float d_m[(size_t)N_NODES * HDIM];
__device__ float d_GX[(size_t)N_NODES * 192];
__device__ float d_GH[(size_t)N_NODES * 192];
__device__ float d_Bmat[64 * TCOLS];
__device__ float d_invdeg[N_NODES];
__device__ int   d_row_start[N_NODES + 1];
__device__ int   d_counts[N_NODES];
__device__ int   d_fill[N_NODES];
__device__ int   d_elist[E_EDGES];
__device__ int   d_partials[128];

// ---------------- f32x2 helpers ----------------
typedef unsigned long long u64;

__device__ __forceinline__ void ffma2(u64 &acc, u64 a, u64 b) {
    asm("fma.rn.f32x2 %0, %1, %2, %0;" : "+l"(acc) : "l"(a), "l"(b));
}
__device__ __forceinline__ u64 pk2(float x, float y) {
    u64 r; asm("mov.b64 %0, {%1, %2};" : "=l"(r) : "f"(x), "f"(y)); return r;
}
__device__ __forceinline__ float2 up2(u64 v) {
    float2 r; asm("mov.b64 {%0, %1}, %2;" : "=f"(r.x), "=f"(r.y) : "l"(v)); return r;
}
__device__ __forceinline__ float sigmoidf_(float x) { return 1.f / (1.f + expf(-x)); }

// ---------------- GEMM: C[nrows x jcols] = act( A[nrows x 64] @ B[64 x jcols] (+C) (+bias) )
// BM=128 rows, BN=64 cols per block, 256 threads, 8x4 per thread, f32x2 FMAs.
__global__ __launch_bounds__(256) void k_gemm(
    const float* __restrict__ A, const float* __restrict__ B,
    float* __restrict__ C, const float* __restrict__ bias,
    int nrows, int jcols, int accum, int act)
{
    __shared__ float As[64][128];   // [k][m]  32 KB
    __shared__ float Bs[64][64];    // [k][j]  16 KB

    const int tid  = threadIdx.x;
    const int row0 = blockIdx.x * 128;
    const int col0 = blockIdx.y * 64;

    // Load A tile, transposed into As[k][m]
#pragma unroll
    for (int p = 0; p < 8; ++p) {
        int f  = p * 256 + tid;          // 0..2047 float4 slots
        int r  = f >> 4;                 // 0..127
        int kq = f & 15;                 // 0..15
        float4 v = make_float4(0.f, 0.f, 0.f, 0.f);
        int grow = row0 + r;
        if (grow < nrows) v = *(const float4*)(A + (size_t)grow * 64 + kq * 4);
        As[kq * 4 + 0][r] = v.x; As[kq * 4 + 1][r] = v.y;
        As[kq * 4 + 2][r] = v.z; As[kq * 4 + 3][r] = v.w;
    }
    // Load B tile
#pragma unroll
    for (int p = 0; p < 4; ++p) {
        int f  = p * 256 + tid;          // 0..1023 float4 slots
        int k  = f >> 4;
        int jq = f & 15;
        *(float4*)&Bs[k][jq * 4] = *(const float4*)(B + (size_t)k * jcols + col0 + jq * 4);
    }
    __syncthreads();

    const int tx = tid & 15, ty = tid >> 4;
    const int mbase = ty * 8, jbase = tx * 4;

    u64 acc[4][4] = {};  // [row-pair][col]

#pragma unroll 16
    for (int k = 0; k < 64; ++k) {
        ulonglong2 a01 = *(const ulonglong2*)&As[k][mbase];      // rows 0,1 | 2,3
        ulonglong2 a23 = *(const ulonglong2*)&As[k][mbase + 4];  // rows 4,5 | 6,7
        float4 b = *(const float4*)&Bs[k][jbase];
        u64 b0 = pk2(b.x, b.x), b1 = pk2(b.y, b.y);
        u64 b2 = pk2(b.z, b.z), b3 = pk2(b.w, b.w);
        ffma2(acc[0][0], a01.x, b0); ffma2(acc[0][1], a01.x, b1);
        ffma2(acc[0][2], a01.x, b2); ffma2(acc[0][3], a01.x, b3);
        ffma2(acc[1][0], a01.y, b0); ffma2(acc[1][1], a01.y, b1);
        ffma2(acc[1][2], a01.y, b2); ffma2(acc[1][3], a01.y, b3);
        ffma2(acc[2][0], a23.x, b0); ffma2(acc[2][1], a23.x, b1);
        ffma2(acc[2][2], a23.x, b2); ffma2(acc[2][3], a23.x, b3);
        ffma2(acc[3][0], a23.y, b0); ffma2(acc[3][1], a23.y, b1);
        ffma2(acc[3][2], a23.y, b2); ffma2(acc[3][3], a23.y, b3);
    }

#pragma unroll
    for (int rp = 0; rp < 4; ++rp) {
        int rbase = row0 + mbase + rp * 2;
#pragma unroll
        for (int cc = 0; cc < 4; ++cc) {
            float2 v = up2(acc[rp][cc]);
            int gcol = col0 + jbase + cc;
            float bv = bias ? bias[gcol] : 0.f;
#pragma unroll
            for (int half = 0; half < 2; ++half) {
                int grow = rbase + half;
                if (grow < nrows) {
                    size_t idx = (size_t)grow * jcols + gcol;
                    float s = half ? v.y : v.x;
                    if (accum) s += C[idx];
                    s += bv;
                    if (act == 1) s = fmaxf(s, 0.f);
                    else if (act == 2) s = sigmoidf_(s);
                    C[idx] = s;
                }
            }
        }
    }
}

// ---------------- CSR build ----------------
__global__ void k_zero(int* counts, int* fill, float* out) {
    int i = blockIdx.x * blockDim.x + threadIdx.x;
    if (i < N_NODES) { counts[i] = 0; fill[i] = 0; }
    if (i < NGRAPH * ODIM) out[i] = 0.f;
}
__global__ void k_hist(const int* __restrict__ ei, int* __restrict__ counts) {
    int e = blockIdx.x * blockDim.x + threadIdx.x;
    if (e < E_EDGES) atomicAdd(&counts[ei[E_EDGES + e]], 1);
}
__global__ void k_scan1(const int* __restrict__ counts, int* __restrict__ incl,
                        int* __restrict__ partials) {
    __shared__ int s[1024];
    int i = blockIdx.x * 1024 + threadIdx.x;
    int v = (i < N_NODES) ? counts[i] : 0;
    s[threadIdx.x] = v; __syncthreads();
    for (int off = 1; off < 1024; off <<= 1) {
        int t = 0;
        if (threadIdx.x >= off) t = s[threadIdx.x - off];
        __syncthreads();
        s[threadIdx.x] += t; __syncthreads();
    }
    if (i < N_NODES) incl[i] = s[threadIdx.x];
    if (threadIdx.x == 1023) partials[blockIdx.x] = s[1023];
}
__global__ void k_scan2(int* partials, int nb) {
    if (threadIdx.x == 0 && blockIdx.x == 0) {
        int run = 0;
        for (int b = 0; b < nb; ++b) { int t = partials[b]; partials[b] = run; run += t; }
    }
}
__global__ void k_scan3(int* __restrict__ rs, const int* __restrict__ partials,
                        const int* __restrict__ counts, float* __restrict__ invdeg) {
    int i = blockIdx.x * blockDim.x + threadIdx.x;
    if (i < N_NODES) {
        rs[i + 1] += partials[i >> 10];
        if (i == 0) rs[0] = 0;
        invdeg[i] = 1.f / fmaxf((float)counts[i], 1.f);
    }
}
__global__ void k_scatter(const int* __restrict__ ei, const int* __restrict__ ea,
                          const int* __restrict__ rs, int* __restrict__ fill,
                          int* __restrict__ elist) {
    int e = blockIdx.x * blockDim.x + threadIdx.x;
    if (e < E_EDGES) {
        int dst = ei[E_EDGES + e];
        int src = ei[e];
        int t   = ea[e];
        int pos = rs[dst] + atomicAdd(&fill[dst], 1);
        elist[pos] = src | (t << 17);
    }
}

// ---------------- misc prep ----------------
__global__ void k_prepB(const float* __restrict__ ee, float* __restrict__ Bm) {
    int i = blockIdx.x * blockDim.x + threadIdx.x;   // 64*320
    if (i >= 64 * TCOLS) return;
    int k = i / TCOLS, j = i % TCOLS;
    int t = j >> 6, c = j & 63;
    Bm[i] = ee[t * 4096 + k * 64 + c];
}
__global__ void k_lin0(const float* __restrict__ x, const float* __restrict__ w,
                       const float* __restrict__ b, float* __restrict__ out0,
                       float* __restrict__ h) {
    __shared__ float sw[15 * 64];
    __shared__ float sb[64];
    __shared__ float sx[4][16];
    int tid = threadIdx.x;
    for (int i = tid; i < 960; i += 256) sw[i] = w[i];
    if (tid < 64) sb[tid] = b[tid];
    int g = tid >> 6, c = tid & 63;
    int n = blockIdx.x * 4 + g;
    if (n < N_NODES && c < 15) sx[g][c] = x[(size_t)n * 15 + c];
    __syncthreads();
    if (n >= N_NODES) return;
    float acc = sb[c];
#pragma unroll
    for (int k = 0; k < 15; ++k) acc += sx[g][k] * sw[k * 64 + c];
    float v = fmaxf(acc, 0.f);
    out0[(size_t)n * 64 + c] = v;
    h[(size_t)n * 64 + c]    = v;
}

// ---------------- aggregation: agg = mean_{in-edges} T[src, type, :]; m = relu(agg + bias)
__global__ void k_aggregate(const float* __restrict__ T, float* __restrict__ m,
                            const int* __restrict__ rs, const int* __restrict__ elist,
                            const float* __restrict__ invdeg,
                            const float* __restrict__ cbias) {
    int g = threadIdx.x >> 6, c = threadIdx.x & 63;
    int n = blockIdx.x * 4 + g;
    if (n >= N_NODES) return;
    int s = rs[n], e = rs[n + 1];
    float acc = 0.f;
    int i = s;
    for (; i + 1 < e; i += 2) {
        int p0 = __ldg(&elist[i]);
        int p1 = __ldg(&elist[i + 1]);
        acc += __ldg(&T[(size_t)(p0 & 131071) * TCOLS + ((p0 >> 17) << 6) + c]);
        acc += __ldg(&T[(size_t)(p1 & 131071) * TCOLS + ((p1 >> 17) << 6) + c]);
    }
    if (i < e) {
        int p0 = __ldg(&elist[i]);
        acc += __ldg(&T[(size_t)(p0 & 131071) * TCOLS + ((p0 >> 17) << 6) + c]);
    }
    m[(size_t)n * 64 + c] = fmaxf(acc * invdeg[n] + cbias[c], 0.f);
}

// ---------------- GRU elementwise update (in place on h) ----------------
__global__ void k_gru(const float* __restrict__ GX, const float* __restrict__ GH,
                      float* __restrict__ h) {
    int idx = blockIdx.x * blockDim.x + threadIdx.x;
    if (idx >= N_NODES * 64) return;
    int n = idx >> 6, c = idx & 63;
    size_t b = (size_t)n * 192 + c;
    float xr = GX[b], xz = GX[b + 64], xn = GX[b + 128];
    float hr = GH[b], hz = GH[b + 64], hn = GH[b + 128];
    float r  = sigmoidf_(xr + hr);
    float z  = sigmoidf_(xz + hz);
    float nn = tanhf(xn + r * hn);
    h[idx] = (1.f - z) * nn + z * h[idx];
}

// ---------------- readout tail: gated = sigmoid(h1@iw2+ib2) * (j1@jw2+jb2); segsum by batch
__global__ void k_readout(const float* __restrict__ h1, const float* __restrict__ j1,
                          const int* __restrict__ batch,
                          const float* __restrict__ iw2, const float* __restrict__ ib2,
                          const float* __restrict__ jw2, const float* __restrict__ jb2,
                          float* __restrict__ out) {
    __shared__ float siw2[64 * 12], sjw2[64 * 12];
    __shared__ float sib2[12], sjb2[12];
    __shared__ float sh1[4][64], sj1[4][64];
    __shared__ float sg[4][12];
    __shared__ int   sb[4];
    int tid = threadIdx.x;
    for (int i = tid; i < 768; i += 256) { siw2[i] = iw2[i]; sjw2[i] = jw2[i]; }
    if (tid < 12) { sib2[tid] = ib2[tid]; sjb2[tid] = jb2[tid]; }
    int g = tid >> 6, c = tid & 63;
    int n = blockIdx.x * 4 + g;
    if (n < N_NODES) {
        sh1[g][c] = h1[(size_t)n * 64 + c];
        sj1[g][c] = j1[(size_t)n * 64 + c];
        if (c == 0) sb[g] = batch[n];
    } else if (c == 0) sb[g] = -1;
    __syncthreads();
    if (n < N_NODES && c < 12) {
        float ia = sib2[c], ja = sjb2[c];
#pragma unroll
        for (int k = 0; k < 64; ++k) {
            ia += sh1[g][k] * siw2[k * 12 + c];
            ja += sj1[g][k] * sjw2[k * 12 + c];
        }
        sg[g][c] = sigmoidf_(ia) * ja;
    }
    __syncthreads();
    if (tid < 48) {
        int gg = tid / 12, d = tid % 12;
        int b = sb[gg];
        if (b >= 0 && (gg == 0 || sb[gg - 1] != b)) {
            float v = sg[gg][d];
            for (int g2 = gg + 1; g2 < 4 && sb[g2] == b; ++g2) v += sg[g2][d];
            atomicAdd(&out[b * 12 + d], v);
        }
    }
}

// ---------------- host launcher ----------------
extern "C" void kernel_launch(void* const* d_in, const int* in_sizes, int n_in,
                              void* d_out, int out_size) {
    const float* x         = (const float*)d_in[0];
    const int*   ei        = (const int*)d_in[1];
    const int*   ea        = (const int*)d_in[2];
    const int*   batch     = (const int*)d_in[3];
    const float* lin0_w    = (const float*)d_in[4];
    const float* lin0_b    = (const float*)d_in[5];
    const float* edge_emb  = (const float*)d_in[6];
    const float* conv_bias = (const float*)d_in[7];
    const float* gru_w_ih  = (const float*)d_in[8];
    const float* gru_w_hh  = (const float*)d_in[9];
    const float* gru_b_ih  = (const float*)d_in[10];
    const float* gru_b_hh  = (const float*)d_in[11];
    const float* i_w1      = (const float*)d_in[12];
    const float* i_b1      = (const float*)d_in[13];
    const float* i_w2      = (const float*)d_in[14];
    const float* i_b2      = (const float*)d_in[15];
    const float* j_w1      = (const float*)d_in[16];
    const float* j_b1      = (const float*)d_in[17];
    const float* j_w2      = (const float*)d_in[18];
    const float* j_b2      = (const float*)d_in[19];
    float* out = (float*)d_out;

    float *T, *h, *out0, *m, *GX, *GH, *Bm, *invdeg;
    int *rs, *counts, *fill, *elist, *partials;
    cudaGetSymbolAddress((void**)&T,        d_T);
    cudaGetSymbolAddress((void**)&h,        d_h);
    cudaGetSymbolAddress((void**)&out0,     d_out0);
    cudaGetSymbolAddress((void**)&m,        d_m);
    cudaGetSymbolAddress((void**)&GX,       d_GX);
    cudaGetSymbolAddress((void**)&GH,       d_GH);
    cudaGetSymbolAddress((void**)&Bm,       d_Bmat);
    cudaGetSymbolAddress((void**)&invdeg,   d_invdeg);
    cudaGetSymbolAddress((void**)&rs,       d_row_start);
    cudaGetSymbolAddress((void**)&counts,   d_counts);
    cudaGetSymbolAddress((void**)&fill,     d_fill);
    cudaGetSymbolAddress((void**)&elist,    d_elist);
    cudaGetSymbolAddress((void**)&partials, d_partials);

    const int NB_N    = (N_NODES + 255) / 256;
    const int NB_E    = (E_EDGES + 255) / 256;
    const int NB_NODE4 = (N_NODES + 3) / 4;
    const int NB_SCAN  = (N_NODES + 1023) / 1024;   // 98
    const int GEMM_RB  = (N_NODES + 127) / 128;     // 782

    // CSR build (reused across all 6 steps) + init
    k_zero<<<NB_N, 256>>>(counts, fill, out);
    k_hist<<<NB_E, 256>>>(ei, counts);
    k_scan1<<<NB_SCAN, 1024>>>(counts, rs + 1, partials);
    k_scan2<<<1, 32>>>(partials, NB_SCAN);
    k_scan3<<<NB_N, 256>>>(rs, partials, counts, invdeg);
    k_scatter<<<NB_E, 256>>>(ei, ea, rs, fill, elist);
    k_prepB<<<(64 * TCOLS + 255) / 256, 256>>>(edge_emb, Bm);
    k_lin0<<<NB_NODE4, 256>>>(x, lin0_w, lin0_b, out0, h);

    for (int s = 0; s < NSTEPS; ++s) {
        // T = h @ [W_0|...|W_4]
        k_gemm<<<dim3(GEMM_RB, 5), 256>>>(h, Bm, T, nullptr, N_NODES, 320, 0, 0);
        // per-node mean aggregation + conv bias + relu
        k_aggregate<<<NB_NODE4, 256>>>(T, m, rs, elist, invdeg, conv_bias);
        // GRU gates
        k_gemm<<<dim3(GEMM_RB, 3), 256>>>(m, gru_w_ih, GX, gru_b_ih, N_NODES, 192, 0, 0);
        k_gemm<<<dim3(GEMM_RB, 3), 256>>>(h, gru_w_hh, GH, gru_b_hh, N_NODES, 192, 0, 0);
        k_gru<<<(N_NODES * 64 + 255) / 256, 256>>>(GX, GH, h);
    }

    // readout: h1 = sigmoid([h|out0] @ i_w1 + i_b1), j1 = sigmoid(h @ j_w1 + j_b1)
    float* h1 = GX;                 // reuse scratch
    float* j1 = GX + (size_t)N_NODES * 64;
    k_gemm<<<dim3(GEMM_RB, 1), 256>>>(h, i_w1, h1, nullptr, N_NODES, 64, 0, 0);
    k_gemm<<<dim3(GEMM_RB, 1), 256>>>(out0, i_w1 + 64 * 64, h1, i_b1, N_NODES, 64, 1, 2);
    k_gemm<<<dim3(GEMM_RB, 1), 256>>>(h, j_w1, j1, j_b1, N_NODES, 64, 0, 2);
    k_readout<<<NB_NODE4, 256>>>(h1, j1, batch, i_w2, i_b2, j_w2, j_b2, out);
}

// round 6
// speedup vs baseline: 1.1923x; 1.1923x over previous
#include <cuda_runtime.h>
#include <cuda_bf16.h>
#include <math.h>
#include <stdint.h>

#define N_NODES 100000
#define E_EDGES 3200000
#define HDIM 64
#define NTYPES 5
#define NGRAPH 256
#define ODIM 12
#define NSTEPS 6
#define SCOLS (NTYPES * HDIM)   // 320

// ---------------- static device scratch ----------------
__device__ float d_S[(size_t)N_NODES * SCOLS];     // 128 MB per-type h sums
__device__ float d_MH[(size_t)N_NODES * 128];      // [m | h]
__device__ float d_HO[(size_t)N_NODES * 128];      // [h | out0]
__device__ float d_hg[(size_t)N_NODES * 64];       // dense h for gather
__device__ float d_G[(size_t)N_NODES * 256];       // GRU gate pre-activations (reused as i1/j1)
__device__ float d_BtS[64 * 320];
__device__ float d_BtG[256 * 128];
__device__ float d_Bti[64 * 128];
__device__ float d_Btj[64 * 64];
__device__ float d_b256[256];
__device__ float d_invdeg[N_NODES];
__device__ int   d_row_start[N_NODES + 1];
__device__ int   d_counts[N_NODES];
__device__ int   d_fill[N_NODES];
__device__ int   d_elist[E_EDGES];
__device__ int   d_partials[128];

__device__ __forceinline__ float sigmoidf_(float x) { return 1.f / (1.f + expf(-x)); }
__device__ __forceinline__ float tf32r(float x) {
    float r;
    asm("cvt.rna.tf32.f32 %0, %1;" : "=f"(r) : "f"(x));
    return r;
}

// ---------------- tf32 tensor-core GEMM ----------------
// C[nrows x (64*gridDim.y)] = act( A[nrows x K] @ B[K x N] + bias )
// A: fp32 row-major with leading dim lda. Bt: pre-transposed+tf32 [N][K].
// BM=128, BN=64, BK=32. 128 threads = 4 warps, warp tile 64x32 (m16n8k8 tf32).
__global__ __launch_bounds__(128, 4) void k_mma(
    const float* __restrict__ A, int lda,
    const float* __restrict__ Bt,
    float* __restrict__ C, int ldc,
    const float* __restrict__ bias,
    int nrows, int K, int act)
{
    __shared__ float As[128][36];
    __shared__ float Bs[64][36];

    const int tid  = threadIdx.x;
    const int lane = tid & 31, warp = tid >> 5;
    const int g = lane >> 2, t = lane & 3;
    const int row0 = blockIdx.x * 128;
    const int col0 = blockIdx.y * 64;
    const int wm = (warp >> 1) * 64;
    const int wn = (warp & 1) * 32;

    float d[4][4][4];
#pragma unroll
    for (int a = 0; a < 4; ++a)
#pragma unroll
        for (int b = 0; b < 4; ++b)
#pragma unroll
            for (int c = 0; c < 4; ++c) d[a][b][c] = 0.f;

    for (int k0 = 0; k0 < K; k0 += 32) {
        // stage A tile 128x32 (cvt to tf32)
#pragma unroll
        for (int p = 0; p < 8; ++p) {
            int f = p * 128 + tid;
            int r = f >> 3, j = (f & 7) * 4;
            float4 v = make_float4(0.f, 0.f, 0.f, 0.f);
            if (row0 + r < nrows)
                v = *(const float4*)(A + (size_t)(row0 + r) * lda + k0 + j);
            v.x = tf32r(v.x); v.y = tf32r(v.y); v.z = tf32r(v.z); v.w = tf32r(v.w);
            *(float4*)&As[r][j] = v;
        }
        // stage B tile 64x32 (already tf32)
#pragma unroll
        for (int p = 0; p < 4; ++p) {
            int f = p * 128 + tid;
            int r = f >> 3, j = (f & 7) * 4;
            *(float4*)&Bs[r][j] = *(const float4*)(Bt + (size_t)(col0 + r) * K + k0 + j);
        }
        __syncthreads();

#pragma unroll
        for (int kb = 0; kb < 4; ++kb) {
            int kk = kb * 8;
            uint32_t b0[4], b1[4];
#pragma unroll
            for (int nt = 0; nt < 4; ++nt) {
                b0[nt] = __float_as_uint(Bs[wn + nt * 8 + g][kk + t]);
                b1[nt] = __float_as_uint(Bs[wn + nt * 8 + g][kk + t + 4]);
            }
#pragma unroll
            for (int mt = 0; mt < 4; ++mt) {
                uint32_t a0 = __float_as_uint(As[wm + mt * 16 + g][kk + t]);
                uint32_t a1 = __float_as_uint(As[wm + mt * 16 + g + 8][kk + t]);
                uint32_t a2 = __float_as_uint(As[wm + mt * 16 + g][kk + t + 4]);
                uint32_t a3 = __float_as_uint(As[wm + mt * 16 + g + 8][kk + t + 4]);
#pragma unroll
                for (int nt = 0; nt < 4; ++nt) {
                    asm volatile(
                        "mma.sync.aligned.m16n8k8.row.col.f32.tf32.tf32.f32 "
                        "{%0,%1,%2,%3}, {%4,%5,%6,%7}, {%8,%9}, {%0,%1,%2,%3};"
                        : "+f"(d[mt][nt][0]), "+f"(d[mt][nt][1]),
                          "+f"(d[mt][nt][2]), "+f"(d[mt][nt][3])
                        : "r"(a0), "r"(a1), "r"(a2), "r"(a3),
                          "r"(b0[nt]), "r"(b1[nt]));
                }
            }
        }
        __syncthreads();
    }

    // epilogue
#pragma unroll
    for (int mt = 0; mt < 4; ++mt) {
        int r0 = row0 + wm + mt * 16 + g;
        int r1 = r0 + 8;
#pragma unroll
        for (int nt = 0; nt < 4; ++nt) {
            int c = col0 + wn + nt * 8 + 2 * t;
            float bv0 = bias ? bias[c] : 0.f;
            float bv1 = bias ? bias[c + 1] : 0.f;
            float e0 = d[mt][nt][0] + bv0, e1 = d[mt][nt][1] + bv1;
            float e2 = d[mt][nt][2] + bv0, e3 = d[mt][nt][3] + bv1;
            if (act == 1) {
                e0 = fmaxf(e0, 0.f); e1 = fmaxf(e1, 0.f);
                e2 = fmaxf(e2, 0.f); e3 = fmaxf(e3, 0.f);
            } else if (act == 2) {
                e0 = sigmoidf_(e0); e1 = sigmoidf_(e1);
                e2 = sigmoidf_(e2); e3 = sigmoidf_(e3);
            }
            if (r0 < nrows) *(float2*)(C + (size_t)r0 * ldc + c) = make_float2(e0, e1);
            if (r1 < nrows) *(float2*)(C + (size_t)r1 * ldc + c) = make_float2(e2, e3);
        }
    }
}

// ---------------- CSR build ----------------
__global__ void k_zero(int* counts, int* fill, float* out) {
    int i = blockIdx.x * blockDim.x + threadIdx.x;
    if (i < N_NODES) { counts[i] = 0; fill[i] = 0; }
    if (i < NGRAPH * ODIM) out[i] = 0.f;
}
__global__ void k_hist(const int* __restrict__ ei, int* __restrict__ counts) {
    int e = blockIdx.x * blockDim.x + threadIdx.x;
    if (e < E_EDGES) atomicAdd(&counts[ei[E_EDGES + e]], 1);
}
__global__ void k_scan1(const int* __restrict__ counts, int* __restrict__ incl,
                        int* __restrict__ partials) {
    __shared__ int s[1024];
    int i = blockIdx.x * 1024 + threadIdx.x;
    int v = (i < N_NODES) ? counts[i] : 0;
    s[threadIdx.x] = v; __syncthreads();
    for (int off = 1; off < 1024; off <<= 1) {
        int tv = 0;
        if (threadIdx.x >= off) tv = s[threadIdx.x - off];
        __syncthreads();
        s[threadIdx.x] += tv; __syncthreads();
    }
    if (i < N_NODES) incl[i] = s[threadIdx.x];
    if (threadIdx.x == 1023) partials[blockIdx.x] = s[1023];
}
__global__ void k_scan2(int* partials, int nb) {
    if (threadIdx.x == 0 && blockIdx.x == 0) {
        int run = 0;
        for (int b = 0; b < nb; ++b) { int tv = partials[b]; partials[b] = run; run += tv; }
    }
}
__global__ void k_scan3(int* __restrict__ rs, const int* __restrict__ partials,
                        const int* __restrict__ counts, float* __restrict__ invdeg) {
    int i = blockIdx.x * blockDim.x + threadIdx.x;
    if (i < N_NODES) {
        rs[i + 1] += partials[i >> 10];
        if (i == 0) rs[0] = 0;
        invdeg[i] = 1.f / fmaxf((float)counts[i], 1.f);
    }
}
__global__ void k_scatter(const int* __restrict__ ei, const int* __restrict__ ea,
                          const int* __restrict__ rs, int* __restrict__ fill,
                          int* __restrict__ elist) {
    int e = blockIdx.x * blockDim.x + threadIdx.x;
    if (e < E_EDGES) {
        int dst = ei[E_EDGES + e];
        int src = ei[e];
        int t   = ea[e];
        int pos = rs[dst] + atomicAdd(&fill[dst], 1);
        elist[pos] = src | (t << 17);
    }
}

// ---------------- B-matrix packing (transpose + tf32) ----------------
__global__ void k_packS(const float* __restrict__ ee, float* __restrict__ Bt) {
    int i = blockIdx.x * blockDim.x + threadIdx.x;   // 64*320
    if (i >= 64 * 320) return;
    int n = i / 320, k = i % 320;
    int t = k >> 6, kk = k & 63;
    Bt[i] = tf32r(ee[t * 4096 + kk * 64 + n]);
}
__global__ void k_packG(const float* __restrict__ wih, const float* __restrict__ whh,
                        const float* __restrict__ bih, const float* __restrict__ bhh,
                        float* __restrict__ Bt, float* __restrict__ b256) {
    int i = blockIdx.x * blockDim.x + threadIdx.x;   // 256*128
    if (i < 256) {
        float bv;
        if (i < 128)      bv = bih[i] + bhh[i];
        else if (i < 192) bv = bih[i];
        else              bv = bhh[i - 64];
        b256[i] = bv;
    }
    if (i >= 256 * 128) return;
    int n = i >> 7, k = i & 127;
    float v = 0.f;
    if (k < 64) {
        if (n < 192) v = wih[k * 192 + n];
    } else {
        int kh = k - 64;
        if (n < 128)       v = whh[kh * 192 + n];
        else if (n >= 192) v = whh[kh * 192 + (n - 64)];
    }
    Bt[i] = tf32r(v);
}
__global__ void k_packi(const float* __restrict__ w, float* __restrict__ Bt) {
    int i = blockIdx.x * blockDim.x + threadIdx.x;   // 64*128
    if (i >= 64 * 128) return;
    int n = i >> 7, k = i & 127;
    Bt[i] = tf32r(w[k * 64 + n]);
}
__global__ void k_packj(const float* __restrict__ w, float* __restrict__ Bt) {
    int i = blockIdx.x * blockDim.x + threadIdx.x;   // 64*64
    if (i >= 64 * 64) return;
    int n = i >> 6, k = i & 63;
    Bt[i] = tf32r(w[k * 64 + n]);
}

// ---------------- lin0: out0 = relu(x @ lin0_w + b); h = out0 ----------------
__global__ void k_lin0(const float* __restrict__ x, const float* __restrict__ w,
                       const float* __restrict__ b,
                       float* __restrict__ MH, float* __restrict__ HO,
                       float* __restrict__ hg) {
    __shared__ float sw[15 * 64];
    __shared__ float sb[64];
    __shared__ float sx[4][16];
    int tid = threadIdx.x;
    for (int i = tid; i < 960; i += 256) sw[i] = w[i];
    if (tid < 64) sb[tid] = b[tid];
    int g = tid >> 6, c = tid & 63;
    int n = blockIdx.x * 4 + g;
    if (n < N_NODES && c < 15) sx[g][c] = x[(size_t)n * 15 + c];
    __syncthreads();
    if (n >= N_NODES) return;
    float acc = sb[c];
#pragma unroll
    for (int k = 0; k < 15; ++k) acc += sx[g][k] * sw[k * 64 + c];
    float v = fmaxf(acc, 0.f);
    MH[(size_t)n * 128 + 64 + c] = v;   // h
    HO[(size_t)n * 128 + c]      = v;   // h
    HO[(size_t)n * 128 + 64 + c] = v;   // out0
    hg[(size_t)n * 64 + c]       = v;   // dense h
}

// ---------------- gather: S[n][t][:] = (1/deg) * sum_{in-edges of type t} h[src] ----------------
#define ACC5(tt, vv)                                                    \
    do {                                                                \
        if      (tt == 0) { a0.x+=vv.x; a0.y+=vv.y; a0.z+=vv.z; a0.w+=vv.w; } \
        else if (tt == 1) { a1.x+=vv.x; a1.y+=vv.y; a1.z+=vv.z; a1.w+=vv.w; } \
        else if (tt == 2) { a2.x+=vv.x; a2.y+=vv.y; a2.z+=vv.z; a2.w+=vv.w; } \
        else if (tt == 3) { a3.x+=vv.x; a3.y+=vv.y; a3.z+=vv.z; a3.w+=vv.w; } \
        else              { a4.x+=vv.x; a4.y+=vv.y; a4.z+=vv.z; a4.w+=vv.w; } \
    } while (0)

__global__ __launch_bounds__(256) void k_gather(
    const float* __restrict__ hg, float* __restrict__ S,
    const int* __restrict__ rs, const int* __restrict__ elist,
    const float* __restrict__ invdeg)
{
    int g = threadIdx.x >> 4;
    int c4 = (threadIdx.x & 15) * 4;
    int n = blockIdx.x * 16 + g;
    if (n >= N_NODES) return;
    int s = rs[n], e = rs[n + 1];
    float4 a0 = {0,0,0,0}, a1 = {0,0,0,0}, a2 = {0,0,0,0}, a3 = {0,0,0,0}, a4 = {0,0,0,0};
    int i = s;
    for (; i + 1 < e; i += 2) {
        int p0 = __ldg(&elist[i]);
        int p1 = __ldg(&elist[i + 1]);
        float4 v0 = __ldg((const float4*)(hg + (size_t)(p0 & 131071) * 64 + c4));
        float4 v1 = __ldg((const float4*)(hg + (size_t)(p1 & 131071) * 64 + c4));
        int t0 = p0 >> 17, t1 = p1 >> 17;
        ACC5(t0, v0);
        ACC5(t1, v1);
    }
    if (i < e) {
        int p0 = __ldg(&elist[i]);
        float4 v0 = __ldg((const float4*)(hg + (size_t)(p0 & 131071) * 64 + c4));
        int t0 = p0 >> 17;
        ACC5(t0, v0);
    }
    float id = invdeg[n];
    float* Sp = S + (size_t)n * SCOLS + c4;
    a0.x*=id; a0.y*=id; a0.z*=id; a0.w*=id; *(float4*)(Sp)       = a0;
    a1.x*=id; a1.y*=id; a1.z*=id; a1.w*=id; *(float4*)(Sp + 64)  = a1;
    a2.x*=id; a2.y*=id; a2.z*=id; a2.w*=id; *(float4*)(Sp + 128) = a2;
    a3.x*=id; a3.y*=id; a3.z*=id; a3.w*=id; *(float4*)(Sp + 192) = a3;
    a4.x*=id; a4.y*=id; a4.z*=id; a4.w*=id; *(float4*)(Sp + 256) = a4;
}

// ---------------- GRU elementwise ----------------
__global__ void k_gru(const float* __restrict__ G,
                      float* __restrict__ MH, float* __restrict__ HO,
                      float* __restrict__ hg) {
    int idx = blockIdx.x * blockDim.x + threadIdx.x;
    if (idx >= N_NODES * 64) return;
    int n = idx >> 6, c = idx & 63;
    size_t b = (size_t)n * 256 + c;
    float r  = sigmoidf_(G[b]);
    float z  = sigmoidf_(G[b + 64]);
    float nn = tanhf(G[b + 128] + r * G[b + 192]);
    float hold = MH[(size_t)n * 128 + 64 + c];
    float h = (1.f - z) * nn + z * hold;
    MH[(size_t)n * 128 + 64 + c] = h;
    HO[(size_t)n * 128 + c]      = h;
    hg[idx]                      = h;
}

// ---------------- readout tail ----------------
__global__ void k_readout(const float* __restrict__ h1, const float* __restrict__ j1,
                          const int* __restrict__ batch,
                          const float* __restrict__ iw2, const float* __restrict__ ib2,
                          const float* __restrict__ jw2, const float* __restrict__ jb2,
                          float* __restrict__ out) {
    __shared__ float siw2[64 * 12], sjw2[64 * 12];
    __shared__ float sib2[12], sjb2[12];
    __shared__ float sh1[4][64], sj1[4][64];
    __shared__ float sg[4][12];
    __shared__ int   sb[4];
    int tid = threadIdx.x;
    for (int i = tid; i < 768; i += 256) { siw2[i] = iw2[i]; sjw2[i] = jw2[i]; }
    if (tid < 12) { sib2[tid] = ib2[tid]; sjb2[tid] = jb2[tid]; }
    int g = tid >> 6, c = tid & 63;
    int n = blockIdx.x * 4 + g;
    if (n < N_NODES) {
        sh1[g][c] = h1[(size_t)n * 64 + c];
        sj1[g][c] = j1[(size_t)n * 64 + c];
        if (c == 0) sb[g] = batch[n];
    } else if (c == 0) sb[g] = -1;
    __syncthreads();
    if (n < N_NODES && c < 12) {
        float ia = sib2[c], ja = sjb2[c];
#pragma unroll
        for (int k = 0; k < 64; ++k) {
            ia += sh1[g][k] * siw2[k * 12 + c];
            ja += sj1[g][k] * sjw2[k * 12 + c];
        }
        sg[g][c] = sigmoidf_(ia) * ja;
    }
    __syncthreads();
    if (tid < 48) {
        int gg = tid / 12, dd = tid % 12;
        int b = sb[gg];
        if (b >= 0 && (gg == 0 || sb[gg - 1] != b)) {
            float v = sg[gg][dd];
            for (int g2 = gg + 1; g2 < 4 && sb[g2] == b; ++g2) v += sg[g2][dd];
            atomicAdd(&out[b * 12 + dd], v);
        }
    }
}

// ---------------- host launcher ----------------
extern "C" void kernel_launch(void* const* d_in, const int* in_sizes, int n_in,
                              void* d_out, int out_size) {
    const float* x         = (const float*)d_in[0];
    const int*   ei        = (const int*)d_in[1];
    const int*   ea        = (const int*)d_in[2];
    const int*   batch     = (const int*)d_in[3];
    const float* lin0_w    = (const float*)d_in[4];
    const float* lin0_b    = (const float*)d_in[5];
    const float* edge_emb  = (const float*)d_in[6];
    const float* conv_bias = (const float*)d_in[7];
    const float* gru_w_ih  = (const float*)d_in[8];
    const float* gru_w_hh  = (const float*)d_in[9];
    const float* gru_b_ih  = (const float*)d_in[10];
    const float* gru_b_hh  = (const float*)d_in[11];
    const float* i_w1      = (const float*)d_in[12];
    const float* i_b1      = (const float*)d_in[13];
    const float* i_w2      = (const float*)d_in[14];
    const float* i_b2      = (const float*)d_in[15];
    const float* j_w1      = (const float*)d_in[16];
    const float* j_b1      = (const float*)d_in[17];
    const float* j_w2      = (const float*)d_in[18];
    const float* j_b2      = (const float*)d_in[19];
    float* out = (float*)d_out;

    float *S, *MH, *HO, *hg, *G, *BtS, *BtG, *Bti, *Btj, *b256, *invdeg;
    int *rs, *counts, *fill, *elist, *partials;
    cudaGetSymbolAddress((void**)&S,        d_S);
    cudaGetSymbolAddress((void**)&MH,       d_MH);
    cudaGetSymbolAddress((void**)&HO,       d_HO);
    cudaGetSymbolAddress((void**)&hg,       d_hg);
    cudaGetSymbolAddress((void**)&G,        d_G);
    cudaGetSymbolAddress((void**)&BtS,      d_BtS);
    cudaGetSymbolAddress((void**)&BtG,      d_BtG);
    cudaGetSymbolAddress((void**)&Bti,      d_Bti);
    cudaGetSymbolAddress((void**)&Btj,      d_Btj);
    cudaGetSymbolAddress((void**)&b256,     d_b256);
    cudaGetSymbolAddress((void**)&invdeg,   d_invdeg);
    cudaGetSymbolAddress((void**)&rs,       d_row_start);
    cudaGetSymbolAddress((void**)&counts,   d_counts);
    cudaGetSymbolAddress((void**)&fill,     d_fill);
    cudaGetSymbolAddress((void**)&elist,    d_elist);
    cudaGetSymbolAddress((void**)&partials, d_partials);

    const int NB_N     = (N_NODES + 255) / 256;
    const int NB_E     = (E_EDGES + 255) / 256;
    const int NB_NODE4 = (N_NODES + 3) / 4;
    const int NB_NODE16 = (N_NODES + 15) / 16;
    const int NB_SCAN  = (N_NODES + 1023) / 1024;
    const int MB       = (N_NODES + 127) / 128;     // 782 M-tiles

    // one-time setup: CSR, weight packs, lin0
    k_zero<<<NB_N, 256>>>(counts, fill, out);
    k_hist<<<NB_E, 256>>>(ei, counts);
    k_scan1<<<NB_SCAN, 1024>>>(counts, rs + 1, partials);
    k_scan2<<<1, 32>>>(partials, NB_SCAN);
    k_scan3<<<NB_N, 256>>>(rs, partials, counts, invdeg);
    k_scatter<<<NB_E, 256>>>(ei, ea, rs, fill, elist);
    k_packS<<<(64 * 320 + 255) / 256, 256>>>(edge_emb, BtS);
    k_packG<<<(256 * 128 + 255) / 256, 256>>>(gru_w_ih, gru_w_hh, gru_b_ih, gru_b_hh, BtG, b256);
    k_packi<<<(64 * 128 + 255) / 256, 256>>>(i_w1, Bti);
    k_packj<<<(64 * 64 + 255) / 256, 256>>>(j_w1, Btj);
    k_lin0<<<NB_NODE4, 256>>>(x, lin0_w, lin0_b, MH, HO, hg);

    for (int s = 0; s < NSTEPS; ++s) {
        // per-type neighbor sums (mean-scaled)
        k_gather<<<NB_NODE16, 256>>>(hg, S, rs, elist, invdeg);
        // m = relu(S @ Wstack + conv_bias)  -> MH[:,0:64]
        k_mma<<<dim3(MB, 1), 128>>>(S, 320, BtS, MH, 128, conv_bias, N_NODES, 320, 1);
        // G = [m|h] @ Wgru + bias  (cols: r-sum | z-sum | xn | hn)
        k_mma<<<dim3(MB, 4), 128>>>(MH, 128, BtG, G, 256, b256, N_NODES, 128, 0);
        // GRU update
        k_gru<<<(N_NODES * 64 + 255) / 256, 256>>>(G, MH, HO, hg);
    }

    // readout: i1 = sigmoid([h|out0]@i_w1+b), j1 = sigmoid(h@j_w1+b)
    float* i1 = G;
    float* j1 = G + (size_t)N_NODES * 64;
    k_mma<<<dim3(MB, 1), 128>>>(HO, 128, Bti, i1, 64, i_b1, N_NODES, 128, 2);
    k_mma<<<dim3(MB, 1), 128>>>(HO, 128, Btj, j1, 64, j_b1, N_NODES, 64, 2);
    k_readout<<<NB_NODE4, 256>>>(i1, j1, batch, i_w2, i_b2, j_w2, j_b2, out);
}

// round 7
// speedup vs baseline: 2.0291x; 1.7019x over previous
#include <cuda_runtime.h>
#include <cuda_bf16.h>
#include <math.h>
#include <stdint.h>

#define N_NODES 100000
#define E_EDGES 3200000
#define HDIM 64
#define NTYPES 5
#define NGRAPH 256
#define ODIM 12
#define NSTEPS 6
#define SCOLS (NTYPES * HDIM)   // 320

// ---------------- static device scratch ----------------
__device__ __nv_bfloat16 d_S[(size_t)N_NODES * SCOLS];  // 64 MB per-type h sums (bf16)
__device__ float d_MH[(size_t)N_NODES * 128];           // [m | h]
__device__ float d_HO[(size_t)N_NODES * 128];           // [h | out0]
__device__ __nv_bfloat16 d_hg[(size_t)N_NODES * 64];    // bf16 h for gather
__device__ float d_G[(size_t)N_NODES * 128];            // readout scratch i1/j1
__device__ __nv_bfloat16 d_BtS[64 * 320];               // bf16 [n][k]
__device__ float d_BtG[256 * 128];                      // tf32 [n][k]
__device__ float d_Bti[64 * 128];
__device__ float d_Btj[64 * 64];
__device__ float d_b256[256];
__device__ float d_invdeg[N_NODES];
__device__ int   d_row_start[N_NODES + 1];
__device__ int   d_counts[N_NODES];
__device__ int   d_fill[N_NODES];
__device__ int   d_elist[E_EDGES];
__device__ int   d_partials[128];

__device__ __forceinline__ float sigmoidf_(float x) { return 1.f / (1.f + expf(-x)); }
__device__ __forceinline__ float tf32r(float x) {
    float r;
    asm("cvt.rna.tf32.f32 %0, %1;" : "=f"(r) : "f"(x));
    return r;
}

// ---------------- tf32 tensor-core GEMM (readout) ----------------
// C[nrows x 64] = act( A[nrows x K] @ B[K x 64] + bias ), Bt pre-transposed [64][K]
__global__ __launch_bounds__(128, 4) void k_mma(
    const float* __restrict__ A, int lda,
    const float* __restrict__ Bt,
    float* __restrict__ C, int ldc,
    const float* __restrict__ bias,
    int nrows, int K, int act)
{
    __shared__ float As[128][36];
    __shared__ float Bs[64][36];

    const int tid  = threadIdx.x;
    const int lane = tid & 31, warp = tid >> 5;
    const int g = lane >> 2, t = lane & 3;
    const int row0 = blockIdx.x * 128;
    const int wm = (warp >> 1) * 64;
    const int wn = (warp & 1) * 32;

    float d[4][4][4];
#pragma unroll
    for (int a = 0; a < 4; ++a)
#pragma unroll
        for (int b = 0; b < 4; ++b)
#pragma unroll
            for (int c = 0; c < 4; ++c) d[a][b][c] = 0.f;

    for (int k0 = 0; k0 < K; k0 += 32) {
#pragma unroll
        for (int p = 0; p < 8; ++p) {
            int f = p * 128 + tid;
            int r = f >> 3, j = (f & 7) * 4;
            float4 v = make_float4(0.f, 0.f, 0.f, 0.f);
            if (row0 + r < nrows)
                v = *(const float4*)(A + (size_t)(row0 + r) * lda + k0 + j);
            v.x = tf32r(v.x); v.y = tf32r(v.y); v.z = tf32r(v.z); v.w = tf32r(v.w);
            *(float4*)&As[r][j] = v;
        }
#pragma unroll
        for (int p = 0; p < 4; ++p) {
            int f = p * 128 + tid;
            int r = f >> 3, j = (f & 7) * 4;
            *(float4*)&Bs[r][j] = *(const float4*)(Bt + (size_t)r * K + k0 + j);
        }
        __syncthreads();

#pragma unroll
        for (int kb = 0; kb < 4; ++kb) {
            int kk = kb * 8;
            uint32_t b0[4], b1[4];
#pragma unroll
            for (int nt = 0; nt < 4; ++nt) {
                b0[nt] = __float_as_uint(Bs[wn + nt * 8 + g][kk + t]);
                b1[nt] = __float_as_uint(Bs[wn + nt * 8 + g][kk + t + 4]);
            }
#pragma unroll
            for (int mt = 0; mt < 4; ++mt) {
                uint32_t a0 = __float_as_uint(As[wm + mt * 16 + g][kk + t]);
                uint32_t a1 = __float_as_uint(As[wm + mt * 16 + g + 8][kk + t]);
                uint32_t a2 = __float_as_uint(As[wm + mt * 16 + g][kk + t + 4]);
                uint32_t a3 = __float_as_uint(As[wm + mt * 16 + g + 8][kk + t + 4]);
#pragma unroll
                for (int nt = 0; nt < 4; ++nt) {
                    asm volatile(
                        "mma.sync.aligned.m16n8k8.row.col.f32.tf32.tf32.f32 "
                        "{%0,%1,%2,%3}, {%4,%5,%6,%7}, {%8,%9}, {%0,%1,%2,%3};"
                        : "+f"(d[mt][nt][0]), "+f"(d[mt][nt][1]),
                          "+f"(d[mt][nt][2]), "+f"(d[mt][nt][3])
                        : "r"(a0), "r"(a1), "r"(a2), "r"(a3),
                          "r"(b0[nt]), "r"(b1[nt]));
                }
            }
        }
        __syncthreads();
    }

#pragma unroll
    for (int mt = 0; mt < 4; ++mt) {
        int r0 = row0 + wm + mt * 16 + g;
        int r1 = r0 + 8;
#pragma unroll
        for (int nt = 0; nt < 4; ++nt) {
            int c = wn + nt * 8 + 2 * t;
            float bv0 = bias ? bias[c] : 0.f;
            float bv1 = bias ? bias[c + 1] : 0.f;
            float e0 = d[mt][nt][0] + bv0, e1 = d[mt][nt][1] + bv1;
            float e2 = d[mt][nt][2] + bv0, e3 = d[mt][nt][3] + bv1;
            if (act == 2) {
                e0 = sigmoidf_(e0); e1 = sigmoidf_(e1);
                e2 = sigmoidf_(e2); e3 = sigmoidf_(e3);
            }
            if (r0 < nrows) *(float2*)(C + (size_t)r0 * ldc + c) = make_float2(e0, e1);
            if (r1 < nrows) *(float2*)(C + (size_t)r1 * ldc + c) = make_float2(e2, e3);
        }
    }
}

// ---------------- bf16 S-GEMM: m = relu(S @ Wstack + conv_bias) -> MH[:,0:64] ----------------
__global__ __launch_bounds__(128, 4) void k_smma(
    const __nv_bfloat16* __restrict__ S, const __nv_bfloat16* __restrict__ Bt,
    float* __restrict__ C, const float* __restrict__ bias, int nrows)
{
    __shared__ __nv_bfloat16 As[128][40];
    __shared__ __nv_bfloat16 Bs[64][40];

    const int tid  = threadIdx.x;
    const int lane = tid & 31, warp = tid >> 5;
    const int g = lane >> 2, t = lane & 3;
    const int row0 = blockIdx.x * 128;
    const int wm = (warp >> 1) * 64;
    const int wn = (warp & 1) * 32;

    float d[4][4][4];
#pragma unroll
    for (int a = 0; a < 4; ++a)
#pragma unroll
        for (int b = 0; b < 4; ++b)
#pragma unroll
            for (int c = 0; c < 4; ++c) d[a][b][c] = 0.f;

    for (int k0 = 0; k0 < 320; k0 += 32) {
        // stage A: 128 rows x 32 bf16 (4 uint4/thread)
#pragma unroll
        for (int p = 0; p < 4; ++p) {
            int f = p * 128 + tid;          // 0..511
            int r = f >> 2, j = (f & 3) * 8;
            uint4 v = make_uint4(0, 0, 0, 0);
            if (row0 + r < nrows)
                v = *(const uint4*)(S + (size_t)(row0 + r) * 320 + k0 + j);
            *(uint4*)&As[r][j] = v;
        }
        // stage B: 64 rows x 32 bf16 (2 uint4/thread)
#pragma unroll
        for (int p = 0; p < 2; ++p) {
            int f = p * 128 + tid;          // 0..255
            int r = f >> 2, j = (f & 3) * 8;
            *(uint4*)&Bs[r][j] = *(const uint4*)(Bt + (size_t)r * 320 + k0 + j);
        }
        __syncthreads();

#pragma unroll
        for (int kb = 0; kb < 2; ++kb) {
            int kk = kb * 16;
            uint32_t b0[4], b1[4];
#pragma unroll
            for (int nt = 0; nt < 4; ++nt) {
                b0[nt] = *(const uint32_t*)&Bs[wn + nt * 8 + g][kk + 2 * t];
                b1[nt] = *(const uint32_t*)&Bs[wn + nt * 8 + g][kk + 2 * t + 8];
            }
#pragma unroll
            for (int mt = 0; mt < 4; ++mt) {
                uint32_t a0 = *(const uint32_t*)&As[wm + mt * 16 + g][kk + 2 * t];
                uint32_t a1 = *(const uint32_t*)&As[wm + mt * 16 + g + 8][kk + 2 * t];
                uint32_t a2 = *(const uint32_t*)&As[wm + mt * 16 + g][kk + 2 * t + 8];
                uint32_t a3 = *(const uint32_t*)&As[wm + mt * 16 + g + 8][kk + 2 * t + 8];
#pragma unroll
                for (int nt = 0; nt < 4; ++nt) {
                    asm volatile(
                        "mma.sync.aligned.m16n8k16.row.col.f32.bf16.bf16.f32 "
                        "{%0,%1,%2,%3}, {%4,%5,%6,%7}, {%8,%9}, {%0,%1,%2,%3};"
                        : "+f"(d[mt][nt][0]), "+f"(d[mt][nt][1]),
                          "+f"(d[mt][nt][2]), "+f"(d[mt][nt][3])
                        : "r"(a0), "r"(a1), "r"(a2), "r"(a3),
                          "r"(b0[nt]), "r"(b1[nt]));
                }
            }
        }
        __syncthreads();
    }

#pragma unroll
    for (int mt = 0; mt < 4; ++mt) {
        int r0 = row0 + wm + mt * 16 + g;
        int r1 = r0 + 8;
#pragma unroll
        for (int nt = 0; nt < 4; ++nt) {
            int c = wn + nt * 8 + 2 * t;
            float bv0 = bias[c], bv1 = bias[c + 1];
            float e0 = fmaxf(d[mt][nt][0] + bv0, 0.f);
            float e1 = fmaxf(d[mt][nt][1] + bv1, 0.f);
            float e2 = fmaxf(d[mt][nt][2] + bv0, 0.f);
            float e3 = fmaxf(d[mt][nt][3] + bv1, 0.f);
            if (r0 < nrows) *(float2*)(C + (size_t)r0 * 128 + c) = make_float2(e0, e1);
            if (r1 < nrows) *(float2*)(C + (size_t)r1 * 128 + c) = make_float2(e2, e3);
        }
    }
}

// ---------------- fused GRU: G=[m|h]@Wgru (tf32), gate math + h update in epilogue ----------------
// 64 rows/block, 4 warps; warp w covers cols {w*16+sub*8.. } of EACH gate block.
__global__ __launch_bounds__(128) void k_grumma(
    const float* __restrict__ MHin, const float* __restrict__ BtG,
    const float* __restrict__ b256,
    float* __restrict__ MH, float* __restrict__ HO, __nv_bfloat16* __restrict__ hg,
    int nrows)
{
    __shared__ float As[64][36];
    __shared__ float Bs[256][36];

    const int tid  = threadIdx.x;
    const int lane = tid & 31, warp = tid >> 5;
    const int g = lane >> 2, t = lane & 3;
    const int row0 = blockIdx.x * 64;

    float d[4][8][4];
#pragma unroll
    for (int a = 0; a < 4; ++a)
#pragma unroll
        for (int b = 0; b < 8; ++b)
#pragma unroll
            for (int c = 0; c < 4; ++c) d[a][b][c] = 0.f;

    for (int k0 = 0; k0 < 128; k0 += 32) {
#pragma unroll
        for (int p = 0; p < 4; ++p) {
            int f = p * 128 + tid;          // 0..511
            int r = f >> 3, j = (f & 7) * 4;
            float4 v = make_float4(0.f, 0.f, 0.f, 0.f);
            if (row0 + r < nrows)
                v = *(const float4*)(MHin + (size_t)(row0 + r) * 128 + k0 + j);
            v.x = tf32r(v.x); v.y = tf32r(v.y); v.z = tf32r(v.z); v.w = tf32r(v.w);
            *(float4*)&As[r][j] = v;
        }
#pragma unroll
        for (int p = 0; p < 16; ++p) {
            int f = p * 128 + tid;          // 0..2047
            int r = f >> 3, j = (f & 7) * 4;
            *(float4*)&Bs[r][j] = *(const float4*)(BtG + (size_t)r * 128 + k0 + j);
        }
        __syncthreads();

#pragma unroll
        for (int kb = 0; kb < 4; ++kb) {
            int kk = kb * 8;
            uint32_t b0[8], b1[8];
#pragma unroll
            for (int nt = 0; nt < 8; ++nt) {
                int nrow = (nt >> 1) * 64 + warp * 16 + (nt & 1) * 8 + g;
                b0[nt] = __float_as_uint(Bs[nrow][kk + t]);
                b1[nt] = __float_as_uint(Bs[nrow][kk + t + 4]);
            }
#pragma unroll
            for (int mt = 0; mt < 4; ++mt) {
                uint32_t a0 = __float_as_uint(As[mt * 16 + g][kk + t]);
                uint32_t a1 = __float_as_uint(As[mt * 16 + g + 8][kk + t]);
                uint32_t a2 = __float_as_uint(As[mt * 16 + g][kk + t + 4]);
                uint32_t a3 = __float_as_uint(As[mt * 16 + g + 8][kk + t + 4]);
#pragma unroll
                for (int nt = 0; nt < 8; ++nt) {
                    asm volatile(
                        "mma.sync.aligned.m16n8k8.row.col.f32.tf32.tf32.f32 "
                        "{%0,%1,%2,%3}, {%4,%5,%6,%7}, {%8,%9}, {%0,%1,%2,%3};"
                        : "+f"(d[mt][nt][0]), "+f"(d[mt][nt][1]),
                          "+f"(d[mt][nt][2]), "+f"(d[mt][nt][3])
                        : "r"(a0), "r"(a1), "r"(a2), "r"(a3),
                          "r"(b0[nt]), "r"(b1[nt]));
                }
            }
        }
        __syncthreads();
    }

    // epilogue: d[mt][sub]=r, d[mt][2+sub]=z, d[mt][4+sub]=xn, d[mt][6+sub]=hn
#pragma unroll
    for (int mt = 0; mt < 4; ++mt) {
#pragma unroll
        for (int sub = 0; sub < 2; ++sub) {
            int cb = warp * 16 + sub * 8 + 2 * t;
#pragma unroll
            for (int f = 0; f < 4; ++f) {
                int row = row0 + mt * 16 + g + ((f & 2) ? 8 : 0);
                int c = cb + (f & 1);
                if (row < nrows) {
                    float rr = sigmoidf_(d[mt][sub][f]     + __ldg(&b256[c]));
                    float zz = sigmoidf_(d[mt][2 + sub][f] + __ldg(&b256[64 + c]));
                    float nv = tanhf(d[mt][4 + sub][f] + __ldg(&b256[128 + c])
                               + rr * (d[mt][6 + sub][f] + __ldg(&b256[192 + c])));
                    float ho = MH[(size_t)row * 128 + 64 + c];
                    float hn = (1.f - zz) * nv + zz * ho;
                    MH[(size_t)row * 128 + 64 + c] = hn;
                    HO[(size_t)row * 128 + c]      = hn;
                    hg[(size_t)row * 64 + c] = __float2bfloat16(hn);
                }
            }
        }
    }
}

// ---------------- CSR build ----------------
__global__ void k_zero(int* counts, int* fill, float* out) {
    int i = blockIdx.x * blockDim.x + threadIdx.x;
    if (i < N_NODES) { counts[i] = 0; fill[i] = 0; }
    if (i < NGRAPH * ODIM) out[i] = 0.f;
}
__global__ void k_hist(const int* __restrict__ ei, int* __restrict__ counts) {
    int e = blockIdx.x * blockDim.x + threadIdx.x;
    if (e < E_EDGES) atomicAdd(&counts[ei[E_EDGES + e]], 1);
}
__global__ void k_scan1(const int* __restrict__ counts, int* __restrict__ incl,
                        int* __restrict__ partials) {
    __shared__ int s[1024];
    int i = blockIdx.x * 1024 + threadIdx.x;
    int v = (i < N_NODES) ? counts[i] : 0;
    s[threadIdx.x] = v; __syncthreads();
    for (int off = 1; off < 1024; off <<= 1) {
        int tv = 0;
        if (threadIdx.x >= off) tv = s[threadIdx.x - off];
        __syncthreads();
        s[threadIdx.x] += tv; __syncthreads();
    }
    if (i < N_NODES) incl[i] = s[threadIdx.x];
    if (threadIdx.x == 1023) partials[blockIdx.x] = s[1023];
}
__global__ void k_scan2(int* partials, int nb) {
    if (threadIdx.x == 0 && blockIdx.x == 0) {
        int run = 0;
        for (int b = 0; b < nb; ++b) { int tv = partials[b]; partials[b] = run; run += tv; }
    }
}
__global__ void k_scan3(int* __restrict__ rs, const int* __restrict__ partials,
                        const int* __restrict__ counts, float* __restrict__ invdeg) {
    int i = blockIdx.x * blockDim.x + threadIdx.x;
    if (i < N_NODES) {
        rs[i + 1] += partials[i >> 10];
        if (i == 0) rs[0] = 0;
        invdeg[i] = 1.f / fmaxf((float)counts[i], 1.f);
    }
}
__global__ void k_scatter(const int* __restrict__ ei, const int* __restrict__ ea,
                          const int* __restrict__ rs, int* __restrict__ fill,
                          int* __restrict__ elist) {
    int e = blockIdx.x * blockDim.x + threadIdx.x;
    if (e < E_EDGES) {
        int dst = ei[E_EDGES + e];
        int src = ei[e];
        int t   = ea[e];
        int pos = rs[dst] + atomicAdd(&fill[dst], 1);
        elist[pos] = src | (t << 17);
    }
}

// ---------------- weight packing ----------------
__global__ void k_packS(const float* __restrict__ ee, __nv_bfloat16* __restrict__ Bt) {
    int i = blockIdx.x * blockDim.x + threadIdx.x;   // 64*320
    if (i >= 64 * 320) return;
    int n = i / 320, k = i % 320;
    int t = k >> 6, kk = k & 63;
    Bt[i] = __float2bfloat16(ee[t * 4096 + kk * 64 + n]);
}
__global__ void k_packG(const float* __restrict__ wih, const float* __restrict__ whh,
                        const float* __restrict__ bih, const float* __restrict__ bhh,
                        float* __restrict__ Bt, float* __restrict__ b256) {
    int i = blockIdx.x * blockDim.x + threadIdx.x;   // 256*128
    if (i < 256) {
        float bv;
        if (i < 128)      bv = bih[i] + bhh[i];
        else if (i < 192) bv = bih[i];
        else              bv = bhh[i - 64];
        b256[i] = bv;
    }
    if (i >= 256 * 128) return;
    int n = i >> 7, k = i & 127;
    float v = 0.f;
    if (k < 64) {
        if (n < 192) v = wih[k * 192 + n];
    } else {
        int kh = k - 64;
        if (n < 128)       v = whh[kh * 192 + n];
        else if (n >= 192) v = whh[kh * 192 + (n - 64)];
    }
    Bt[i] = tf32r(v);
}
__global__ void k_packi(const float* __restrict__ w, float* __restrict__ Bt) {
    int i = blockIdx.x * blockDim.x + threadIdx.x;   // 64*128
    if (i >= 64 * 128) return;
    int n = i >> 7, k = i & 127;
    Bt[i] = tf32r(w[k * 64 + n]);
}
__global__ void k_packj(const float* __restrict__ w, float* __restrict__ Bt) {
    int i = blockIdx.x * blockDim.x + threadIdx.x;   // 64*64
    if (i >= 64 * 64) return;
    int n = i >> 6, k = i & 63;
    Bt[i] = tf32r(w[k * 64 + n]);
}

// ---------------- lin0 ----------------
__global__ void k_lin0(const float* __restrict__ x, const float* __restrict__ w,
                       const float* __restrict__ b,
                       float* __restrict__ MH, float* __restrict__ HO,
                       __nv_bfloat16* __restrict__ hg) {
    __shared__ float sw[15 * 64];
    __shared__ float sb[64];
    __shared__ float sx[4][16];
    int tid = threadIdx.x;
    for (int i = tid; i < 960; i += 256) sw[i] = w[i];
    if (tid < 64) sb[tid] = b[tid];
    int g = tid >> 6, c = tid & 63;
    int n = blockIdx.x * 4 + g;
    if (n < N_NODES && c < 15) sx[g][c] = x[(size_t)n * 15 + c];
    __syncthreads();
    if (n >= N_NODES) return;
    float acc = sb[c];
#pragma unroll
    for (int k = 0; k < 15; ++k) acc += sx[g][k] * sw[k * 64 + c];
    float v = fmaxf(acc, 0.f);
    MH[(size_t)n * 128 + 64 + c] = v;   // h
    HO[(size_t)n * 128 + c]      = v;   // h
    HO[(size_t)n * 128 + 64 + c] = v;   // out0
    hg[(size_t)n * 64 + c] = __float2bfloat16(v);
}

// ---------------- gather (bf16): S[n][t][:] = invdeg * sum_{type-t in-edges} h[src] --------
#define UNPACK8(v, f0, f1, f2, f3)                                      \
    float2 f0 = __bfloat1622float2(((const __nv_bfloat162*)&(v))[0]);   \
    float2 f1 = __bfloat1622float2(((const __nv_bfloat162*)&(v))[1]);   \
    float2 f2 = __bfloat1622float2(((const __nv_bfloat162*)&(v))[2]);   \
    float2 f3 = __bfloat1622float2(((const __nv_bfloat162*)&(v))[3]);

#define ADD8(SA, SB, f0, f1, f2, f3)                                    \
    { SA.x += f0.x; SA.y += f0.y; SA.z += f1.x; SA.w += f1.y;           \
      SB.x += f2.x; SB.y += f2.y; SB.z += f3.x; SB.w += f3.y; }

#define ACC8(tt, f0, f1, f2, f3)                                        \
    do {                                                                \
        if      (tt == 0) ADD8(s0a, s0b, f0, f1, f2, f3)                \
        else if (tt == 1) ADD8(s1a, s1b, f0, f1, f2, f3)                \
        else if (tt == 2) ADD8(s2a, s2b, f0, f1, f2, f3)                \
        else if (tt == 3) ADD8(s3a, s3b, f0, f1, f2, f3)                \
        else              ADD8(s4a, s4b, f0, f1, f2, f3)                \
    } while (0)

__device__ __forceinline__ void st8(__nv_bfloat16* p, float4 a, float4 b, float id) {
    uint4 o;
    ((__nv_bfloat162*)&o)[0] = __floats2bfloat162_rn(a.x * id, a.y * id);
    ((__nv_bfloat162*)&o)[1] = __floats2bfloat162_rn(a.z * id, a.w * id);
    ((__nv_bfloat162*)&o)[2] = __floats2bfloat162_rn(b.x * id, b.y * id);
    ((__nv_bfloat162*)&o)[3] = __floats2bfloat162_rn(b.z * id, b.w * id);
    *(uint4*)p = o;
}

__global__ __launch_bounds__(256) void k_gather(
    const __nv_bfloat16* __restrict__ hg, __nv_bfloat16* __restrict__ S,
    const int* __restrict__ rs, const int* __restrict__ elist,
    const float* __restrict__ invdeg)
{
    int g = threadIdx.x >> 3;            // node slot 0..31
    int c8 = (threadIdx.x & 7) * 8;      // col base
    int n = blockIdx.x * 32 + g;
    if (n >= N_NODES) return;
    int s = rs[n], e = rs[n + 1];
    float4 s0a = {0,0,0,0}, s0b = {0,0,0,0}, s1a = {0,0,0,0}, s1b = {0,0,0,0};
    float4 s2a = {0,0,0,0}, s2b = {0,0,0,0}, s3a = {0,0,0,0}, s3b = {0,0,0,0};
    float4 s4a = {0,0,0,0}, s4b = {0,0,0,0};
    int i = s;
    for (; i + 1 < e; i += 2) {
        int p0 = __ldg(&elist[i]);
        int p1 = __ldg(&elist[i + 1]);
        uint4 v0 = __ldg((const uint4*)(hg + (size_t)(p0 & 131071) * 64 + c8));
        uint4 v1 = __ldg((const uint4*)(hg + (size_t)(p1 & 131071) * 64 + c8));
        int t0 = p0 >> 17, t1 = p1 >> 17;
        { UNPACK8(v0, f0, f1, f2, f3); ACC8(t0, f0, f1, f2, f3); }
        { UNPACK8(v1, f0, f1, f2, f3); ACC8(t1, f0, f1, f2, f3); }
    }
    if (i < e) {
        int p0 = __ldg(&elist[i]);
        uint4 v0 = __ldg((const uint4*)(hg + (size_t)(p0 & 131071) * 64 + c8));
        int t0 = p0 >> 17;
        { UNPACK8(v0, f0, f1, f2, f3); ACC8(t0, f0, f1, f2, f3); }
    }
    float id = invdeg[n];
    __nv_bfloat16* Sp = S + (size_t)n * SCOLS + c8;
    st8(Sp,        s0a, s0b, id);
    st8(Sp + 64,   s1a, s1b, id);
    st8(Sp + 128,  s2a, s2b, id);
    st8(Sp + 192,  s3a, s3b, id);
    st8(Sp + 256,  s4a, s4b, id);
}

// ---------------- readout tail ----------------
__global__ void k_readout(const float* __restrict__ h1, const float* __restrict__ j1,
                          const int* __restrict__ batch,
                          const float* __restrict__ iw2, const float* __restrict__ ib2,
                          const float* __restrict__ jw2, const float* __restrict__ jb2,
                          float* __restrict__ out) {
    __shared__ float siw2[64 * 12], sjw2[64 * 12];
    __shared__ float sib2[12], sjb2[12];
    __shared__ float sh1[4][64], sj1[4][64];
    __shared__ float sg[4][12];
    __shared__ int   sb[4];
    int tid = threadIdx.x;
    for (int i = tid; i < 768; i += 256) { siw2[i] = iw2[i]; sjw2[i] = jw2[i]; }
    if (tid < 12) { sib2[tid] = ib2[tid]; sjb2[tid] = jb2[tid]; }
    int g = tid >> 6, c = tid & 63;
    int n = blockIdx.x * 4 + g;
    if (n < N_NODES) {
        sh1[g][c] = h1[(size_t)n * 64 + c];
        sj1[g][c] = j1[(size_t)n * 64 + c];
        if (c == 0) sb[g] = batch[n];
    } else if (c == 0) sb[g] = -1;
    __syncthreads();
    if (n < N_NODES && c < 12) {
        float ia = sib2[c], ja = sjb2[c];
#pragma unroll
        for (int k = 0; k < 64; ++k) {
            ia += sh1[g][k] * siw2[k * 12 + c];
            ja += sj1[g][k] * sjw2[k * 12 + c];
        }
        sg[g][c] = sigmoidf_(ia) * ja;
    }
    __syncthreads();
    if (tid < 48) {
        int gg = tid / 12, dd = tid % 12;
        int b = sb[gg];
        if (b >= 0 && (gg == 0 || sb[gg - 1] != b)) {
            float v = sg[gg][dd];
            for (int g2 = gg + 1; g2 < 4 && sb[g2] == b; ++g2) v += sg[g2][dd];
            atomicAdd(&out[b * 12 + dd], v);
        }
    }
}

// ---------------- host launcher ----------------
extern "C" void kernel_launch(void* const* d_in, const int* in_sizes, int n_in,
                              void* d_out, int out_size) {
    const float* x         = (const float*)d_in[0];
    const int*   ei        = (const int*)d_in[1];
    const int*   ea        = (const int*)d_in[2];
    const int*   batch     = (const int*)d_in[3];
    const float* lin0_w    = (const float*)d_in[4];
    const float* lin0_b    = (const float*)d_in[5];
    const float* edge_emb  = (const float*)d_in[6];
    const float* conv_bias = (const float*)d_in[7];
    const float* gru_w_ih  = (const float*)d_in[8];
    const float* gru_w_hh  = (const float*)d_in[9];
    const float* gru_b_ih  = (const float*)d_in[10];
    const float* gru_b_hh  = (const float*)d_in[11];
    const float* i_w1      = (const float*)d_in[12];
    const float* i_b1      = (const float*)d_in[13];
    const float* i_w2      = (const float*)d_in[14];
    const float* i_b2      = (const float*)d_in[15];
    const float* j_w1      = (const float*)d_in[16];
    const float* j_b1      = (const float*)d_in[17];
    const float* j_w2      = (const float*)d_in[18];
    const float* j_b2      = (const float*)d_in[19];
    float* out = (float*)d_out;

    __nv_bfloat16 *S, *hg, *BtS;
    float *MH, *HO, *G, *BtG, *Bti, *Btj, *b256, *invdeg;
    int *rs, *counts, *fill, *elist, *partials;
    cudaGetSymbolAddress((void**)&S,        d_S);
    cudaGetSymbolAddress((void**)&MH,       d_MH);
    cudaGetSymbolAddress((void**)&HO,       d_HO);
    cudaGetSymbolAddress((void**)&hg,       d_hg);
    cudaGetSymbolAddress((void**)&G,        d_G);
    cudaGetSymbolAddress((void**)&BtS,      d_BtS);
    cudaGetSymbolAddress((void**)&BtG,      d_BtG);
    cudaGetSymbolAddress((void**)&Bti,      d_Bti);
    cudaGetSymbolAddress((void**)&Btj,      d_Btj);
    cudaGetSymbolAddress((void**)&b256,     d_b256);
    cudaGetSymbolAddress((void**)&invdeg,   d_invdeg);
    cudaGetSymbolAddress((void**)&rs,       d_row_start);
    cudaGetSymbolAddress((void**)&counts,   d_counts);
    cudaGetSymbolAddress((void**)&fill,     d_fill);
    cudaGetSymbolAddress((void**)&elist,    d_elist);
    cudaGetSymbolAddress((void**)&partials, d_partials);

    const int NB_N      = (N_NODES + 255) / 256;
    const int NB_E      = (E_EDGES + 255) / 256;
    const int NB_NODE4  = (N_NODES + 3) / 4;
    const int NB_NODE32 = (N_NODES + 31) / 32;
    const int NB_SCAN   = (N_NODES + 1023) / 1024;
    const int MB        = (N_NODES + 127) / 128;    // 782
    const int GB        = (N_NODES + 63) / 64;      // 1563

    // one-time setup: CSR, weight packs, lin0
    k_zero<<<NB_N, 256>>>(counts, fill, out);
    k_hist<<<NB_E, 256>>>(ei, counts);
    k_scan1<<<NB_SCAN, 1024>>>(counts, rs + 1, partials);
    k_scan2<<<1, 32>>>(partials, NB_SCAN);
    k_scan3<<<NB_N, 256>>>(rs, partials, counts, invdeg);
    k_scatter<<<NB_E, 256>>>(ei, ea, rs, fill, elist);
    k_packS<<<(64 * 320 + 255) / 256, 256>>>(edge_emb, BtS);
    k_packG<<<(256 * 128 + 255) / 256, 256>>>(gru_w_ih, gru_w_hh, gru_b_ih, gru_b_hh, BtG, b256);
    k_packi<<<(64 * 128 + 255) / 256, 256>>>(i_w1, Bti);
    k_packj<<<(64 * 64 + 255) / 256, 256>>>(j_w1, Btj);
    k_lin0<<<NB_NODE4, 256>>>(x, lin0_w, lin0_b, MH, HO, hg);

    for (int s = 0; s < NSTEPS; ++s) {
        // per-type neighbor sums (mean-scaled), bf16
        k_gather<<<NB_NODE32, 256>>>(hg, S, rs, elist, invdeg);
        // m = relu(S @ Wstack + conv_bias)  -> MH[:,0:64]
        k_smma<<<MB, 128>>>(S, BtS, MH, conv_bias, N_NODES);
        // fused: gates GEMM + GRU update -> MH h, HO h, hg
        k_grumma<<<GB, 128>>>(MH, BtG, b256, MH, HO, hg, N_NODES);
    }

    // readout: i1 = sigmoid([h|out0]@i_w1+b), j1 = sigmoid(h@j_w1+b)
    float* i1 = G;
    float* j1 = G + (size_t)N_NODES * 64;
    k_mma<<<MB, 128>>>(HO, 128, Bti, i1, 64, i_b1, N_NODES, 128, 2);
    k_mma<<<MB, 128>>>(HO, 128, Btj, j1, 64, j_b1, N_NODES, 64, 2);
    k_readout<<<NB_NODE4, 256>>>(i1, j1, batch, i_w2, i_b2, j_w2, j_b2, out);
}